// round 6
// baseline (speedup 1.0000x reference)
#include <cuda_runtime.h>
#include <math.h>

// Problem constants (fixed by the reference)
#define BB    4096
#define AA    3
#define HH    13
#define WW    13
#define CC    5
#define NT    32
#define CH    (5 + CC)          // 10 channels per anchor
#define HW    (HH * WW)         // 169
#define NCELL (AA * HW)         // 507

// Per-batch partial results, SoA for coalesced final reduce.
__device__ float g_obj[BB];
__device__ float g_bbox[BB];
__device__ float g_cls[BB];
__device__ unsigned int g_done = 0;   // last-block counter; reset each run by the last block

__device__ __forceinline__ float bce_logits_fast(float x, float t) {
    // max(x,0) - x*t + softplus(-|x|); fast-math softplus (abs err < 1e-7)
    return fmaxf(x, 0.0f) - x * t + __logf(1.0f + __expf(-fabsf(x)));
}

__global__ void __launch_bounds__(256)
sgs_loss_fused(const float* __restrict__ pred,
               const float* __restrict__ tboxes,
               const long long* __restrict__ tlabels,
               const float* __restrict__ anchors,
               float* __restrict__ out, int B)
{
    __shared__ int    s_win[NCELL];      // last-wins winner (bbox/obj scatter)
    __shared__ int    s_win_cls[NCELL];  // last-wins winner (cls scatter)
    __shared__ float  s_tbox[NT][4];
    __shared__ int    s_lab[NT];
    __shared__ float  s_red[8][5];
    __shared__ int    s_islast;
    __shared__ double s_dred[8][3];

    const int b   = blockIdx.x;
    const int tid = threadIdx.x;

    for (int i = tid; i < NCELL; i += 256) { s_win[i] = -1; s_win_cls[i] = -1; }
    __syncthreads();

    // ---- per-target processing (threads 0..31) ----
    if (tid < NT) {
        float4 box = ((const float4*)tboxes)[b * NT + tid];
        float cx = box.x, cy = box.y, w = box.z, h = box.w;
        bool valid = (cx > 0.0f) && (cx < 1.0f) && (cy > 0.0f) && (cy < 1.0f)
                  && (w > 0.0f) && (h > 0.0f);
        float ws = valid ? w : 1.0f;
        float hs = valid ? h : 1.0f;
        int gx = (int)(cx * (float)WW); gx = min(max(gx, 0), WW - 1);
        int gy = (int)(cy * (float)HH); gy = min(max(gy, 0), HH - 1);

        // argmax IoU over anchors (first occurrence on ties, matching jnp.argmax)
        int   besta = 0;
        float bestiou = -1.0f, baw = 1.0f, bah = 1.0f;
        #pragma unroll
        for (int a = 0; a < AA; a++) {
            float aw = anchors[a * 2 + 0];
            float ah = anchors[a * 2 + 1];
            float inter = fminf(ws, aw) * fminf(hs, ah);
            float iou = inter / (ws * hs + aw * ah - inter);
            if (iou > bestiou) { bestiou = iou; besta = a; baw = aw; bah = ah; }
        }

        s_tbox[tid][0] = cx * (float)WW - (float)gx;
        s_tbox[tid][1] = cy * (float)HH - (float)gy;
        s_tbox[tid][2] = logf(ws / baw + 1e-16f);   // precise (feeds squared loss)
        s_tbox[tid][3] = logf(hs / bah + 1e-16f);

        long long lb = tlabels[b * NT + tid];
        bool labok = (lb >= 0) && (lb < (long long)CC);
        long long lc = lb < 0 ? 0 : (lb > (long long)(CC - 1) ? (long long)(CC - 1) : lb);
        s_lab[tid] = (int)lc;

        if (valid) {
            int cell = besta * HW + gy * WW + gx;
            atomicMax(&s_win[cell], tid);          // last-update-wins
            if (labok) atomicMax(&s_win_cls[cell], tid);
        }
    }
    __syncthreads();

    // ---- main loss loop over 507 cells ----
    float neg = 0.0f, pos = 0.0f, bsum = 0.0f, csum = 0.0f;
    int   cnt = 0;
    const float* pb = pred + (size_t)b * (AA * CH * HW);

    for (int cidx = tid; cidx < NCELL; cidx += 256) {
        int a  = cidx / HW;
        int hw = cidx - a * HW;
        const float* cp = pb + a * CH * HW + hw;

        float po = cp[0];
        int wg = s_win[cidx];
        if (wg < 0) {
            neg += bce_logits_fast(po, 0.0f);
        } else {
            pos += bce_logits_fast(po, 1.0f);
            cnt++;
            #pragma unroll
            for (int j = 0; j < 4; j++) {
                float d = cp[(1 + j) * HW] - s_tbox[wg][j];
                bsum += d * d;
            }
            int wc = s_win_cls[cidx];
            int lb = (wc >= 0) ? s_lab[wc] : -1;
            #pragma unroll
            for (int c = 0; c < CC; c++) {
                csum += bce_logits_fast(cp[(5 + c) * HW], (c == lb) ? 1.0f : 0.0f);
            }
        }
    }

    // ---- block reduction of {neg, pos, bsum, csum, cnt} ----
    float v[5] = {neg, pos, bsum, csum, (float)cnt};
    #pragma unroll
    for (int o = 16; o > 0; o >>= 1) {
        #pragma unroll
        for (int k = 0; k < 5; k++) v[k] += __shfl_down_sync(0xFFFFFFFFu, v[k], o);
    }
    int wid = tid >> 5, lid = tid & 31;
    if (lid == 0) {
        #pragma unroll
        for (int k = 0; k < 5; k++) s_red[wid][k] = v[k];
    }
    __syncthreads();

    if (tid == 0) {
        float rn = 0, rp = 0, rb = 0, rc = 0, rcnt = 0;
        #pragma unroll
        for (int w2 = 0; w2 < 8; w2++) {
            rn += s_red[w2][0]; rp += s_red[w2][1]; rb += s_red[w2][2];
            rc += s_red[w2][3]; rcnt += s_red[w2][4];
        }
        float npos = rcnt;
        float pw = ((float)NCELL - npos) / (npos + 1e-16f);
        float obj_b  = (rn + pw * rp) / (float)NCELL;
        float bbox_b = (npos > 0.0f) ? rb / (4.0f * npos + 1e-30f) : 0.0f;
        float cls_b  = (npos > 0.0f) ? rc / ((float)CC * npos + 1e-30f) : 0.0f;
        g_obj[b]  = obj_b;
        g_bbox[b] = bbox_b;
        g_cls[b]  = cls_b;
    }

    // ---- last-block final reduction (L2-hot SoA scratch, no extra launch) ----
    __threadfence();
    if (tid == 0) {
        unsigned int t = atomicAdd(&g_done, 1u);
        s_islast = (t == (unsigned int)(gridDim.x - 1)) ? 1 : 0;
    }
    __syncthreads();
    if (!s_islast) return;

    double o = 0.0, bb = 0.0, cl = 0.0;
    for (int i = tid; i < B; i += 256) {        // coalesced SoA loads, full MLP
        o  += (double)g_obj[i];
        bb += (double)g_bbox[i];
        cl += (double)g_cls[i];
    }
    #pragma unroll
    for (int off = 16; off > 0; off >>= 1) {
        o  += __shfl_down_sync(0xFFFFFFFFu, o,  off);
        bb += __shfl_down_sync(0xFFFFFFFFu, bb, off);
        cl += __shfl_down_sync(0xFFFFFFFFu, cl, off);
    }
    if (lid == 0) { s_dred[wid][0] = o; s_dred[wid][1] = bb; s_dred[wid][2] = cl; }
    __syncthreads();
    if (tid == 0) {
        double ro = 0.0, rb = 0.0, rc = 0.0;
        #pragma unroll
        for (int w2 = 0; w2 < 8; w2++) {
            ro += s_dred[w2][0]; rb += s_dred[w2][1]; rc += s_dred[w2][2];
        }
        float objf  = (float)(ro / (double)B);
        float bboxf = (float)(rb / (double)B);
        float clsf  = (float)(rc / (double)B);
        out[0] = 2.0f * objf + 5.0f * bboxf + 2.0f * clsf;
        out[1] = objf;
        out[2] = bboxf;
        out[3] = clsf;
        g_done = 0;   // reset for next graph replay
    }
}

extern "C" void kernel_launch(void* const* d_in, const int* in_sizes, int n_in,
                              void* d_out, int out_size)
{
    const float*     pred    = (const float*)d_in[0];
    const float*     tboxes  = (const float*)d_in[1];
    const long long* tlabels = (const long long*)d_in[2];
    const float*     anchors = (const float*)d_in[3];
    float*           out     = (float*)d_out;

    int B = in_sizes[0] / (AA * CH * HW);
    if (B > BB) B = BB;

    sgs_loss_fused<<<B, 256>>>(pred, tboxes, tlabels, anchors, out, B);
}

// round 8
// speedup vs baseline: 1.3072x; 1.3072x over previous
#include <cuda_runtime.h>
#include <math.h>

// Problem constants (fixed by the reference)
#define BB    4096
#define AA    3
#define HH    13
#define WW    13
#define CC    5
#define NT    32
#define CH    (5 + CC)          // 10 channels per anchor
#define HW    (HH * WW)         // 169
#define NCELL (AA * HW)         // 507

// Per-batch partial results, SoA for coalesced reduce.
__device__ float g_obj[BB];
__device__ float g_bbox[BB];
__device__ float g_cls[BB];

__device__ __forceinline__ float softplus_fast(float x) {
    // softplus(x) = max(x,0) + log(1+exp(-|x|)); fast-math (abs err < 1e-7)
    return fmaxf(x, 0.0f) + __logf(1.0f + __expf(-fabsf(x)));
}

__global__ void __launch_bounds__(256)
sgs_loss_per_batch(const float* __restrict__ pred,
                   const float* __restrict__ tboxes,
                   const long long* __restrict__ tlabels,
                   const float* __restrict__ anchors)
{
    __shared__ int   s_win[NCELL];      // last-wins winner (bbox/obj scatter)
    __shared__ int   s_win_cls[NCELL];  // last-wins winner (cls scatter)
    __shared__ float s_tbox[NT][4];
    __shared__ int   s_lab[NT];
    __shared__ float s_red[8][5];

    const int b   = blockIdx.x;
    const int tid = threadIdx.x;
    const float* pb = pred + (size_t)b * (AA * CH * HW);

    for (int i = tid; i < NCELL; i += 256) { s_win[i] = -1; s_win_cls[i] = -1; }

    // ---- prefetch objectness logits BEFORE the target phase ----
    // These LDGs have no dependency on the scatter; issuing them here hides the
    // warp-0 target-processing chain under their DRAM latency.
    const int c0 = tid;            // cell 0
    const int c1 = tid + 256;      // cell 1 (may be out of range)
    int a0 = c0 / HW, hw0 = c0 - a0 * HW;
    int a1 = c1 / HW, hw1 = c1 - a1 * HW;
    float po0 = pb[a0 * CH * HW + hw0];
    float po1 = (c1 < NCELL) ? pb[a1 * CH * HW + hw1] : 0.0f;

    __syncthreads();   // s_win init visible before warp-0 atomics

    // ---- per-target processing (threads 0..31) ----
    if (tid < NT) {
        float4 box = ((const float4*)tboxes)[b * NT + tid];
        float cx = box.x, cy = box.y, w = box.z, h = box.w;
        bool valid = (cx > 0.0f) && (cx < 1.0f) && (cy > 0.0f) && (cy < 1.0f)
                  && (w > 0.0f) && (h > 0.0f);
        float ws = valid ? w : 1.0f;
        float hs = valid ? h : 1.0f;
        int gx = (int)(cx * (float)WW); gx = min(max(gx, 0), WW - 1);
        int gy = (int)(cy * (float)HH); gy = min(max(gy, 0), HH - 1);

        // argmax IoU over anchors (first occurrence on ties, matching jnp.argmax)
        int   besta = 0;
        float bestiou = -1.0f, baw = 1.0f, bah = 1.0f;
        #pragma unroll
        for (int a = 0; a < AA; a++) {
            float aw = anchors[a * 2 + 0];
            float ah = anchors[a * 2 + 1];
            float inter = fminf(ws, aw) * fminf(hs, ah);
            float iou = inter / (ws * hs + aw * ah - inter);
            if (iou > bestiou) { bestiou = iou; besta = a; baw = aw; bah = ah; }
        }

        s_tbox[tid][0] = cx * (float)WW - (float)gx;
        s_tbox[tid][1] = cy * (float)HH - (float)gy;
        s_tbox[tid][2] = __logf(ws / baw + 1e-16f);   // feeds squared loss; fast log OK
        s_tbox[tid][3] = __logf(hs / bah + 1e-16f);

        long long lb = tlabels[b * NT + tid];
        bool labok = (lb >= 0) && (lb < (long long)CC);
        long long lc = lb < 0 ? 0 : (lb > (long long)(CC - 1) ? (long long)(CC - 1) : lb);
        s_lab[tid] = (int)lc;

        if (valid) {
            int cell = besta * HW + gy * WW + gx;
            atomicMax(&s_win[cell], tid);          // last-update-wins
            if (labok) atomicMax(&s_win_cls[cell], tid);
        }
    }
    __syncthreads();

    // ---- main loss over 507 cells (obj logits already in registers) ----
    float neg = 0.0f, pos = 0.0f, bsum = 0.0f, csum = 0.0f;
    int   cnt = 0;

    #pragma unroll
    for (int it = 0; it < 2; it++) {
        int cidx = (it == 0) ? c0 : c1;
        if (cidx >= NCELL) break;
        float po = (it == 0) ? po0 : po1;
        int a  = (it == 0) ? a0 : a1;
        int hw = (it == 0) ? hw0 : hw1;

        float sp = softplus_fast(po);   // bce(x,0)=sp ; bce(x,1)=sp-x
        int wg = s_win[cidx];
        if (wg < 0) {
            neg += sp;
        } else {
            pos += sp - po;
            cnt++;
            const float* cp = pb + a * CH * HW + hw;
            #pragma unroll
            for (int j = 0; j < 4; j++) {
                float d = cp[(1 + j) * HW] - s_tbox[wg][j];
                bsum += d * d;
            }
            int wc = s_win_cls[cidx];
            int lb = (wc >= 0) ? s_lab[wc] : -1;
            #pragma unroll
            for (int c = 0; c < CC; c++) {
                float pc = cp[(5 + c) * HW];
                csum += softplus_fast(pc) - ((c == lb) ? pc : 0.0f);
            }
        }
    }

    // ---- block reduction of {neg, pos, bsum, csum, cnt} ----
    float v[5] = {neg, pos, bsum, csum, (float)cnt};
    #pragma unroll
    for (int o = 16; o > 0; o >>= 1) {
        #pragma unroll
        for (int k = 0; k < 5; k++) v[k] += __shfl_down_sync(0xFFFFFFFFu, v[k], o);
    }
    int wid = tid >> 5, lid = tid & 31;
    if (lid == 0) {
        #pragma unroll
        for (int k = 0; k < 5; k++) s_red[wid][k] = v[k];
    }
    __syncthreads();

    if (tid == 0) {
        float rn = 0, rp = 0, rb = 0, rc = 0, rcnt = 0;
        #pragma unroll
        for (int w2 = 0; w2 < 8; w2++) {
            rn += s_red[w2][0]; rp += s_red[w2][1]; rb += s_red[w2][2];
            rc += s_red[w2][3]; rcnt += s_red[w2][4];
        }
        float npos = rcnt;
        float pw = ((float)NCELL - npos) / (npos + 1e-16f);
        float obj_b  = (rn + pw * rp) / (float)NCELL;
        float bbox_b = (npos > 0.0f) ? rb / (4.0f * npos + 1e-30f) : 0.0f;
        float cls_b  = (npos > 0.0f) ? rc / ((float)CC * npos + 1e-30f) : 0.0f;
        g_obj[b]  = obj_b;
        g_bbox[b] = bbox_b;
        g_cls[b]  = cls_b;
    }
}

__global__ void __launch_bounds__(256)
sgs_loss_reduce(float* __restrict__ out, int B)
{
    __shared__ double s_red[8][3];
    const int tid = threadIdx.x;
    double o = 0.0, bb = 0.0, cl = 0.0;
    for (int i = tid; i < B; i += 256) {        // coalesced SoA loads
        o  += (double)g_obj[i];
        bb += (double)g_bbox[i];
        cl += (double)g_cls[i];
    }
    #pragma unroll
    for (int off = 16; off > 0; off >>= 1) {
        o  += __shfl_down_sync(0xFFFFFFFFu, o,  off);
        bb += __shfl_down_sync(0xFFFFFFFFu, bb, off);
        cl += __shfl_down_sync(0xFFFFFFFFu, cl, off);
    }
    int wid = tid >> 5, lid = tid & 31;
    if (lid == 0) { s_red[wid][0] = o; s_red[wid][1] = bb; s_red[wid][2] = cl; }
    __syncthreads();
    if (tid == 0) {
        double ro = 0.0, rb = 0.0, rc = 0.0;
        #pragma unroll
        for (int w2 = 0; w2 < 8; w2++) {
            ro += s_red[w2][0]; rb += s_red[w2][1]; rc += s_red[w2][2];
        }
        float obj  = (float)(ro / (double)B);
        float bbox = (float)(rb / (double)B);
        float cls  = (float)(rc / (double)B);
        out[0] = 2.0f * obj + 5.0f * bbox + 2.0f * cls;
        out[1] = obj;
        out[2] = bbox;
        out[3] = cls;
    }
}

extern "C" void kernel_launch(void* const* d_in, const int* in_sizes, int n_in,
                              void* d_out, int out_size)
{
    const float*     pred    = (const float*)d_in[0];
    const float*     tboxes  = (const float*)d_in[1];
    const long long* tlabels = (const long long*)d_in[2];
    const float*     anchors = (const float*)d_in[3];
    float*           out     = (float*)d_out;

    int B = in_sizes[0] / (AA * CH * HW);
    if (B > BB) B = BB;

    sgs_loss_per_batch<<<B, 256>>>(pred, tboxes, tlabels, anchors);
    sgs_loss_reduce<<<1, 256>>>(out, B);
}

// round 11
// speedup vs baseline: 1.4654x; 1.1211x over previous
#include <cuda_runtime.h>
#include <math.h>

// Problem constants (fixed by the reference)
#define BB    4096
#define AA    3
#define HH    13
#define WW    13
#define CC    5
#define NT    32
#define CH    (5 + CC)          // 10 channels per anchor
#define HW    (HH * WW)         // 169
#define NCELL (AA * HW)         // 507

#define TPB   128               // threads per block (4 cells per thread)
#define NIT   4                 // ceil(507/128)

// Per-batch partial results, SoA for coalesced reduce.
__device__ float g_obj[BB];
__device__ float g_bbox[BB];
__device__ float g_cls[BB];

__device__ __forceinline__ float softplus_fast(float x) {
    // softplus(x) = max(x,0) + log(1+exp(-|x|)); fast-math (abs err < 1e-7)
    return fmaxf(x, 0.0f) + __logf(1.0f + __expf(-fabsf(x)));
}

__global__ void __launch_bounds__(TPB)
sgs_loss_per_batch(const float* __restrict__ pred,
                   const float* __restrict__ tboxes,
                   const long long* __restrict__ tlabels,
                   const float* __restrict__ anchors)
{
    __shared__ int   s_win[NCELL];      // last-wins winner (bbox/obj scatter)
    __shared__ int   s_win_cls[NCELL];  // last-wins winner (cls scatter)
    __shared__ float s_tbox[NT][4];
    __shared__ int   s_lab[NT];
    __shared__ float s_red[4][5];

    const int b   = blockIdx.x;
    const int tid = threadIdx.x;
    const float* pb = pred + (size_t)b * (AA * CH * HW);

    for (int i = tid; i < NCELL; i += TPB) { s_win[i] = -1; s_win_cls[i] = -1; }

    // ---- prefetch objectness logits BEFORE the target phase ----
    // 4 independent LDGs per thread; no dependency on the scatter, so the
    // warp-0 target-processing chain hides under their DRAM latency.
    int   ac[NIT], hwc[NIT];
    float po[NIT];
    #pragma unroll
    for (int it = 0; it < NIT; it++) {
        int c = tid + it * TPB;
        int a = c / HW, hw = c - a * HW;
        ac[it] = a; hwc[it] = hw;
        po[it] = (c < NCELL) ? pb[a * CH * HW + hw] : 0.0f;
    }

    __syncthreads();   // s_win init visible before warp-0 atomics

    // ---- per-target processing (threads 0..31) ----
    if (tid < NT) {
        float4 box = ((const float4*)tboxes)[b * NT + tid];
        float cx = box.x, cy = box.y, w = box.z, h = box.w;
        bool valid = (cx > 0.0f) && (cx < 1.0f) && (cy > 0.0f) && (cy < 1.0f)
                  && (w > 0.0f) && (h > 0.0f);
        float ws = valid ? w : 1.0f;
        float hs = valid ? h : 1.0f;
        int gx = (int)(cx * (float)WW); gx = min(max(gx, 0), WW - 1);
        int gy = (int)(cy * (float)HH); gy = min(max(gy, 0), HH - 1);

        // argmax IoU over anchors (first occurrence on ties, matching jnp.argmax)
        int   besta = 0;
        float bestiou = -1.0f, baw = 1.0f, bah = 1.0f;
        #pragma unroll
        for (int a = 0; a < AA; a++) {
            float aw = anchors[a * 2 + 0];
            float ah = anchors[a * 2 + 1];
            float inter = fminf(ws, aw) * fminf(hs, ah);
            float iou = inter / (ws * hs + aw * ah - inter);
            if (iou > bestiou) { bestiou = iou; besta = a; baw = aw; bah = ah; }
        }

        s_tbox[tid][0] = cx * (float)WW - (float)gx;
        s_tbox[tid][1] = cy * (float)HH - (float)gy;
        s_tbox[tid][2] = __logf(ws / baw + 1e-16f);   // feeds squared loss; fast log OK
        s_tbox[tid][3] = __logf(hs / bah + 1e-16f);

        long long lb = tlabels[b * NT + tid];
        bool labok = (lb >= 0) && (lb < (long long)CC);
        long long lc = lb < 0 ? 0 : (lb > (long long)(CC - 1) ? (long long)(CC - 1) : lb);
        s_lab[tid] = (int)lc;

        if (valid) {
            int cell = besta * HW + gy * WW + gx;
            atomicMax(&s_win[cell], tid);          // last-update-wins
            if (labok) atomicMax(&s_win_cls[cell], tid);
        }
    }
    __syncthreads();

    // ---- main loss over 507 cells (obj logits already in registers) ----
    float neg = 0.0f, pos = 0.0f, bsum = 0.0f, csum = 0.0f;
    int   cnt = 0;

    #pragma unroll
    for (int it = 0; it < NIT; it++) {
        int cidx = tid + it * TPB;
        if (cidx >= NCELL) break;

        float sp = softplus_fast(po[it]);   // bce(x,0)=sp ; bce(x,1)=sp-x
        int wg = s_win[cidx];
        if (wg < 0) {
            neg += sp;
        } else {
            pos += sp - po[it];
            cnt++;
            const float* cp = pb + ac[it] * CH * HW + hwc[it];
            #pragma unroll
            for (int j = 0; j < 4; j++) {
                float d = cp[(1 + j) * HW] - s_tbox[wg][j];
                bsum += d * d;
            }
            int wc = s_win_cls[cidx];
            int lb = (wc >= 0) ? s_lab[wc] : -1;
            #pragma unroll
            for (int c = 0; c < CC; c++) {
                float pc = cp[(5 + c) * HW];
                csum += softplus_fast(pc) - ((c == lb) ? pc : 0.0f);
            }
        }
    }

    // ---- block reduction of {neg, pos, bsum, csum, cnt} ----
    float v[5] = {neg, pos, bsum, csum, (float)cnt};
    #pragma unroll
    for (int o = 16; o > 0; o >>= 1) {
        #pragma unroll
        for (int k = 0; k < 5; k++) v[k] += __shfl_down_sync(0xFFFFFFFFu, v[k], o);
    }
    int wid = tid >> 5, lid = tid & 31;
    if (lid == 0) {
        #pragma unroll
        for (int k = 0; k < 5; k++) s_red[wid][k] = v[k];
    }
    __syncthreads();

    if (tid == 0) {
        float rn = 0, rp = 0, rb = 0, rc = 0, rcnt = 0;
        #pragma unroll
        for (int w2 = 0; w2 < 4; w2++) {
            rn += s_red[w2][0]; rp += s_red[w2][1]; rb += s_red[w2][2];
            rc += s_red[w2][3]; rcnt += s_red[w2][4];
        }
        float npos = rcnt;
        float pw = ((float)NCELL - npos) / (npos + 1e-16f);
        float obj_b  = (rn + pw * rp) / (float)NCELL;
        float bbox_b = (npos > 0.0f) ? rb / (4.0f * npos + 1e-30f) : 0.0f;
        float cls_b  = (npos > 0.0f) ? rc / ((float)CC * npos + 1e-30f) : 0.0f;
        g_obj[b]  = obj_b;
        g_bbox[b] = bbox_b;
        g_cls[b]  = cls_b;
    }
}

__global__ void __launch_bounds__(256)
sgs_loss_reduce(float* __restrict__ out, int B)
{
    __shared__ double s_red[8][3];
    const int tid = threadIdx.x;
    double o = 0.0, bb = 0.0, cl = 0.0;
    for (int i = tid; i < B; i += 256) {        // coalesced SoA loads
        o  += (double)g_obj[i];
        bb += (double)g_bbox[i];
        cl += (double)g_cls[i];
    }
    #pragma unroll
    for (int off = 16; off > 0; off >>= 1) {
        o  += __shfl_down_sync(0xFFFFFFFFu, o,  off);
        bb += __shfl_down_sync(0xFFFFFFFFu, bb, off);
        cl += __shfl_down_sync(0xFFFFFFFFu, cl, off);
    }
    int wid = tid >> 5, lid = tid & 31;
    if (lid == 0) { s_red[wid][0] = o; s_red[wid][1] = bb; s_red[wid][2] = cl; }
    __syncthreads();
    if (tid == 0) {
        double ro = 0.0, rb = 0.0, rc = 0.0;
        #pragma unroll
        for (int w2 = 0; w2 < 8; w2++) {
            ro += s_red[w2][0]; rb += s_red[w2][1]; rc += s_red[w2][2];
        }
        float obj  = (float)(ro / (double)B);
        float bbox = (float)(rb / (double)B);
        float cls  = (float)(rc / (double)B);
        out[0] = 2.0f * obj + 5.0f * bbox + 2.0f * cls;
        out[1] = obj;
        out[2] = bbox;
        out[3] = cls;
    }
}

extern "C" void kernel_launch(void* const* d_in, const int* in_sizes, int n_in,
                              void* d_out, int out_size)
{
    const float*     pred    = (const float*)d_in[0];
    const float*     tboxes  = (const float*)d_in[1];
    const long long* tlabels = (const long long*)d_in[2];
    const float*     anchors = (const float*)d_in[3];
    float*           out     = (float*)d_out;

    int B = in_sizes[0] / (AA * CH * HW);
    if (B > BB) B = BB;

    sgs_loss_per_batch<<<B, TPB>>>(pred, tboxes, tlabels, anchors);
    sgs_loss_reduce<<<1, 256>>>(out, B);
}

// round 12
// speedup vs baseline: 1.4960x; 1.0209x over previous
#include <cuda_runtime.h>
#include <math.h>

// Problem constants (fixed by the reference)
#define BB    4096
#define AA    3
#define HH    13
#define WW    13
#define CC    5
#define NT    32
#define CH    (5 + CC)          // 10 channels per anchor
#define HW    (HH * WW)         // 169
#define NCELL (AA * HW)         // 507

#define TPB   64                // threads per block (8 cells per thread)
#define NIT   8                 // ceil(507/64)

// Per-batch partial results, SoA for coalesced reduce.
__device__ float g_obj[BB];
__device__ float g_bbox[BB];
__device__ float g_cls[BB];

__device__ __forceinline__ float softplus_fast(float x) {
    // softplus(x) = max(x,0) + log(1+exp(-|x|)); fast-math (abs err < 1e-7)
    return fmaxf(x, 0.0f) + __logf(1.0f + __expf(-fabsf(x)));
}

__global__ void __launch_bounds__(TPB)
sgs_loss_per_batch(const float* __restrict__ pred,
                   const float* __restrict__ tboxes,
                   const long long* __restrict__ tlabels,
                   const float* __restrict__ anchors)
{
    __shared__ int   s_win[NCELL];      // last-wins winner (bbox/obj scatter)
    __shared__ int   s_win_cls[NCELL];  // last-wins winner (cls scatter)
    __shared__ float s_tbox[NT][4];
    __shared__ int   s_lab[NT];
    __shared__ float s_red[2][5];

    const int b   = blockIdx.x;
    const int tid = threadIdx.x;
    const float* pb = pred + (size_t)b * (AA * CH * HW);

    for (int i = tid; i < NCELL; i += TPB) { s_win[i] = -1; s_win_cls[i] = -1; }

    // ---- prefetch objectness logits BEFORE the target phase ----
    // 8 independent LDGs per thread; no dependency on the scatter, so the
    // warp-0 target-processing chain hides under their DRAM latency.
    int   ac[NIT], hwc[NIT];
    float po[NIT];
    #pragma unroll
    for (int it = 0; it < NIT; it++) {
        int c = tid + it * TPB;
        int a = c / HW, hw = c - a * HW;
        ac[it] = a; hwc[it] = hw;
        po[it] = (c < NCELL) ? pb[a * CH * HW + hw] : 0.0f;
    }

    __syncthreads();   // s_win init visible before warp-0 atomics

    // ---- per-target processing (threads 0..31, one target per lane) ----
    if (tid < NT) {
        float4 box = ((const float4*)tboxes)[b * NT + tid];
        float cx = box.x, cy = box.y, w = box.z, h = box.w;
        bool valid = (cx > 0.0f) && (cx < 1.0f) && (cy > 0.0f) && (cy < 1.0f)
                  && (w > 0.0f) && (h > 0.0f);
        float ws = valid ? w : 1.0f;
        float hs = valid ? h : 1.0f;
        int gx = (int)(cx * (float)WW); gx = min(max(gx, 0), WW - 1);
        int gy = (int)(cy * (float)HH); gy = min(max(gy, 0), HH - 1);

        // argmax IoU over anchors (first occurrence on ties, matching jnp.argmax)
        int   besta = 0;
        float bestiou = -1.0f, baw = 1.0f, bah = 1.0f;
        #pragma unroll
        for (int a = 0; a < AA; a++) {
            float aw = anchors[a * 2 + 0];
            float ah = anchors[a * 2 + 1];
            float inter = fminf(ws, aw) * fminf(hs, ah);
            float iou = inter / (ws * hs + aw * ah - inter);
            if (iou > bestiou) { bestiou = iou; besta = a; baw = aw; bah = ah; }
        }

        s_tbox[tid][0] = cx * (float)WW - (float)gx;
        s_tbox[tid][1] = cy * (float)HH - (float)gy;
        s_tbox[tid][2] = __logf(ws / baw + 1e-16f);   // feeds squared loss; fast log OK
        s_tbox[tid][3] = __logf(hs / bah + 1e-16f);

        long long lb = tlabels[b * NT + tid];
        bool labok = (lb >= 0) && (lb < (long long)CC);
        long long lc = lb < 0 ? 0 : (lb > (long long)(CC - 1) ? (long long)(CC - 1) : lb);
        s_lab[tid] = (int)lc;

        if (valid) {
            int cell = besta * HW + gy * WW + gx;
            atomicMax(&s_win[cell], tid);          // last-update-wins
            if (labok) atomicMax(&s_win_cls[cell], tid);
        }
    }
    __syncthreads();

    // ---- main loss over 507 cells (obj logits already in registers) ----
    float neg = 0.0f, pos = 0.0f, bsum = 0.0f, csum = 0.0f;
    int   cnt = 0;

    #pragma unroll
    for (int it = 0; it < NIT; it++) {
        int cidx = tid + it * TPB;
        if (cidx >= NCELL) break;

        float sp = softplus_fast(po[it]);   // bce(x,0)=sp ; bce(x,1)=sp-x
        int wg = s_win[cidx];
        if (wg < 0) {
            neg += sp;
        } else {
            pos += sp - po[it];
            cnt++;
            const float* cp = pb + ac[it] * CH * HW + hwc[it];
            #pragma unroll
            for (int j = 0; j < 4; j++) {
                float d = cp[(1 + j) * HW] - s_tbox[wg][j];
                bsum += d * d;
            }
            int wc = s_win_cls[cidx];
            int lb = (wc >= 0) ? s_lab[wc] : -1;
            #pragma unroll
            for (int c = 0; c < CC; c++) {
                float pc = cp[(5 + c) * HW];
                csum += softplus_fast(pc) - ((c == lb) ? pc : 0.0f);
            }
        }
    }

    // ---- block reduction of {neg, pos, bsum, csum, cnt} (2 warps) ----
    float v[5] = {neg, pos, bsum, csum, (float)cnt};
    #pragma unroll
    for (int o = 16; o > 0; o >>= 1) {
        #pragma unroll
        for (int k = 0; k < 5; k++) v[k] += __shfl_down_sync(0xFFFFFFFFu, v[k], o);
    }
    int wid = tid >> 5, lid = tid & 31;
    if (lid == 0) {
        #pragma unroll
        for (int k = 0; k < 5; k++) s_red[wid][k] = v[k];
    }
    __syncthreads();

    if (tid == 0) {
        float rn = 0, rp = 0, rb = 0, rc = 0, rcnt = 0;
        #pragma unroll
        for (int w2 = 0; w2 < 2; w2++) {
            rn += s_red[w2][0]; rp += s_red[w2][1]; rb += s_red[w2][2];
            rc += s_red[w2][3]; rcnt += s_red[w2][4];
        }
        float npos = rcnt;
        float pw = ((float)NCELL - npos) / (npos + 1e-16f);
        float obj_b  = (rn + pw * rp) / (float)NCELL;
        float bbox_b = (npos > 0.0f) ? rb / (4.0f * npos + 1e-30f) : 0.0f;
        float cls_b  = (npos > 0.0f) ? rc / ((float)CC * npos + 1e-30f) : 0.0f;
        g_obj[b]  = obj_b;
        g_bbox[b] = bbox_b;
        g_cls[b]  = cls_b;
    }
}

__global__ void __launch_bounds__(256)
sgs_loss_reduce(float* __restrict__ out, int B)
{
    __shared__ double s_red[8][3];
    const int tid = threadIdx.x;
    double o = 0.0, bb = 0.0, cl = 0.0;
    for (int i = tid; i < B; i += 256) {        // coalesced SoA loads
        o  += (double)g_obj[i];
        bb += (double)g_bbox[i];
        cl += (double)g_cls[i];
    }
    #pragma unroll
    for (int off = 16; off > 0; off >>= 1) {
        o  += __shfl_down_sync(0xFFFFFFFFu, o,  off);
        bb += __shfl_down_sync(0xFFFFFFFFu, bb, off);
        cl += __shfl_down_sync(0xFFFFFFFFu, cl, off);
    }
    int wid = tid >> 5, lid = tid & 31;
    if (lid == 0) { s_red[wid][0] = o; s_red[wid][1] = bb; s_red[wid][2] = cl; }
    __syncthreads();
    if (tid == 0) {
        double ro = 0.0, rb = 0.0, rc = 0.0;
        #pragma unroll
        for (int w2 = 0; w2 < 8; w2++) {
            ro += s_red[w2][0]; rb += s_red[w2][1]; rc += s_red[w2][2];
        }
        float obj  = (float)(ro / (double)B);
        float bbox = (float)(rb / (double)B);
        float cls  = (float)(rc / (double)B);
        out[0] = 2.0f * obj + 5.0f * bbox + 2.0f * cls;
        out[1] = obj;
        out[2] = bbox;
        out[3] = cls;
    }
}

extern "C" void kernel_launch(void* const* d_in, const int* in_sizes, int n_in,
                              void* d_out, int out_size)
{
    const float*     pred    = (const float*)d_in[0];
    const float*     tboxes  = (const float*)d_in[1];
    const long long* tlabels = (const long long*)d_in[2];
    const float*     anchors = (const float*)d_in[3];
    float*           out     = (float*)d_out;

    int B = in_sizes[0] / (AA * CH * HW);
    if (B > BB) B = BB;

    sgs_loss_per_batch<<<B, TPB>>>(pred, tboxes, tlabels, anchors);
    sgs_loss_reduce<<<1, 256>>>(out, B);
}

// round 13
// speedup vs baseline: 1.6153x; 1.0797x over previous
#include <cuda_runtime.h>
#include <math.h>

// Problem constants (fixed by the reference)
#define BB    4096
#define AA    3
#define HH    13
#define WW    13
#define CC    5
#define NT    32
#define CH    (5 + CC)          // 10 channels per anchor
#define HW    (HH * WW)         // 169
#define NCELL (AA * HW)         // 507

#define TPB   64                // threads per block (8 cells per thread)
#define NIT   8                 // ceil(507/64)

// Per-batch partial results, SoA for coalesced reduce.
__device__ float g_obj[BB];
__device__ float g_bbox[BB];
__device__ float g_cls[BB];

__device__ __forceinline__ float softplus_fast(float x) {
    // softplus(x) = max(x,0) + log(1+exp(-|x|)); fast-math (abs err < 1e-7)
    return fmaxf(x, 0.0f) + __logf(1.0f + __expf(-fabsf(x)));
}

__global__ void __launch_bounds__(TPB)
sgs_loss_per_batch(const float* __restrict__ pred,
                   const float* __restrict__ tboxes,
                   const long long* __restrict__ tlabels,
                   const float* __restrict__ anchors)
{
    __shared__ int   s_win[NCELL];      // last-wins winner (bbox/obj scatter)
    __shared__ int   s_win_cls[NCELL];  // last-wins winner (cls scatter)
    __shared__ float s_tbox[NT][4];
    __shared__ int   s_lab[NT];
    __shared__ float s_red[2][5];

    const int b   = blockIdx.x;
    const int tid = threadIdx.x;
    const float* pb = pred + (size_t)b * (AA * CH * HW);

    for (int i = tid; i < NCELL; i += TPB) { s_win[i] = -1; s_win_cls[i] = -1; }

    // ---- prefetch objectness logits BEFORE the target phase ----
    // 8 independent LDGs per thread; no dependency on the scatter, so the
    // warp-0 target-processing chain hides under their DRAM latency.
    // Only the values are kept in registers; indices are recomputed later.
    float po[NIT];
    #pragma unroll
    for (int it = 0; it < NIT; it++) {
        int c = tid + it * TPB;
        int a = c / HW, hw = c - a * HW;
        po[it] = (c < NCELL) ? pb[a * CH * HW + hw] : 0.0f;
    }

    __syncthreads();   // s_win init visible before warp-0 atomics

    // ---- per-target processing (threads 0..31, one target per lane) ----
    if (tid < NT) {
        float4 box = ((const float4*)tboxes)[b * NT + tid];
        float cx = box.x, cy = box.y, w = box.z, h = box.w;
        bool valid = (cx > 0.0f) && (cx < 1.0f) && (cy > 0.0f) && (cy < 1.0f)
                  && (w > 0.0f) && (h > 0.0f);
        float ws = valid ? w : 1.0f;
        float hs = valid ? h : 1.0f;
        int gx = (int)(cx * (float)WW); gx = min(max(gx, 0), WW - 1);
        int gy = (int)(cy * (float)HH); gy = min(max(gy, 0), HH - 1);

        // argmax IoU over anchors (first occurrence on ties, matching jnp.argmax)
        int   besta = 0;
        float bestiou = -1.0f, baw = 1.0f, bah = 1.0f;
        #pragma unroll
        for (int a = 0; a < AA; a++) {
            float aw = anchors[a * 2 + 0];
            float ah = anchors[a * 2 + 1];
            float inter = fminf(ws, aw) * fminf(hs, ah);
            float iou = inter / (ws * hs + aw * ah - inter);
            if (iou > bestiou) { bestiou = iou; besta = a; baw = aw; bah = ah; }
        }

        s_tbox[tid][0] = cx * (float)WW - (float)gx;
        s_tbox[tid][1] = cy * (float)HH - (float)gy;
        s_tbox[tid][2] = __logf(ws / baw + 1e-16f);   // feeds squared loss; fast log OK
        s_tbox[tid][3] = __logf(hs / bah + 1e-16f);

        long long lb = tlabels[b * NT + tid];
        bool labok = (lb >= 0) && (lb < (long long)CC);
        long long lc = lb < 0 ? 0 : (lb > (long long)(CC - 1) ? (long long)(CC - 1) : lb);
        s_lab[tid] = (int)lc;

        if (valid) {
            int cell = besta * HW + gy * WW + gx;
            atomicMax(&s_win[cell], tid);          // last-update-wins
            if (labok) atomicMax(&s_win_cls[cell], tid);
        }
    }
    __syncthreads();

    // ---- main loss over 507 cells (obj logits already in registers) ----
    float neg = 0.0f, pos = 0.0f, bsum = 0.0f, csum = 0.0f;
    int   cnt = 0;

    #pragma unroll
    for (int it = 0; it < NIT; it++) {
        int cidx = tid + it * TPB;
        if (cidx >= NCELL) break;

        float sp = softplus_fast(po[it]);   // bce(x,0)=sp ; bce(x,1)=sp-x
        int wg = s_win[cidx];
        if (wg < 0) {
            neg += sp;
        } else {
            pos += sp - po[it];
            cnt++;
            int a  = cidx / HW;             // recomputed (mul-shift), no regs held
            int hw = cidx - a * HW;
            const float* cp = pb + a * CH * HW + hw;
            #pragma unroll
            for (int j = 0; j < 4; j++) {
                float d = cp[(1 + j) * HW] - s_tbox[wg][j];
                bsum += d * d;
            }
            int wc = s_win_cls[cidx];
            int lb = (wc >= 0) ? s_lab[wc] : -1;
            #pragma unroll
            for (int c = 0; c < CC; c++) {
                float pc = cp[(5 + c) * HW];
                csum += softplus_fast(pc) - ((c == lb) ? pc : 0.0f);
            }
        }
    }

    // ---- block reduction of {neg, pos, bsum, csum, cnt} (2 warps) ----
    float v[5] = {neg, pos, bsum, csum, (float)cnt};
    #pragma unroll
    for (int o = 16; o > 0; o >>= 1) {
        #pragma unroll
        for (int k = 0; k < 5; k++) v[k] += __shfl_down_sync(0xFFFFFFFFu, v[k], o);
    }
    int wid = tid >> 5, lid = tid & 31;
    if (lid == 0) {
        #pragma unroll
        for (int k = 0; k < 5; k++) s_red[wid][k] = v[k];
    }
    __syncthreads();

    if (tid == 0) {
        float rn = 0, rp = 0, rb = 0, rc = 0, rcnt = 0;
        #pragma unroll
        for (int w2 = 0; w2 < 2; w2++) {
            rn += s_red[w2][0]; rp += s_red[w2][1]; rb += s_red[w2][2];
            rc += s_red[w2][3]; rcnt += s_red[w2][4];
        }
        float npos = rcnt;
        float pw = ((float)NCELL - npos) / (npos + 1e-16f);
        float obj_b  = (rn + pw * rp) / (float)NCELL;
        float bbox_b = (npos > 0.0f) ? rb / (4.0f * npos + 1e-30f) : 0.0f;
        float cls_b  = (npos > 0.0f) ? rc / ((float)CC * npos + 1e-30f) : 0.0f;
        g_obj[b]  = obj_b;
        g_bbox[b] = bbox_b;
        g_cls[b]  = cls_b;
    }
}

// 1024 threads: exactly one float4 per thread per array for B=4096.
__global__ void __launch_bounds__(1024)
sgs_loss_reduce(float* __restrict__ out, int B)
{
    __shared__ double s_red[32][3];
    const int tid = threadIdx.x;
    const int nvec = B >> 2;               // 1024 for B=4096

    double o = 0.0, bb = 0.0, cl = 0.0;
    for (int i = tid; i < nvec; i += 1024) {
        float4 vo = ((const float4*)g_obj)[i];
        float4 vb = ((const float4*)g_bbox)[i];
        float4 vc = ((const float4*)g_cls)[i];
        o  += (double)vo.x + (double)vo.y + (double)vo.z + (double)vo.w;
        bb += (double)vb.x + (double)vb.y + (double)vb.z + (double)vb.w;
        cl += (double)vc.x + (double)vc.y + (double)vc.z + (double)vc.w;
    }
    // tail (B not multiple of 4) — B=4096 so this is empty, kept for safety
    for (int i = (nvec << 2) + tid; i < B; i += 1024) {
        o += (double)g_obj[i]; bb += (double)g_bbox[i]; cl += (double)g_cls[i];
    }

    #pragma unroll
    for (int off = 16; off > 0; off >>= 1) {
        o  += __shfl_down_sync(0xFFFFFFFFu, o,  off);
        bb += __shfl_down_sync(0xFFFFFFFFu, bb, off);
        cl += __shfl_down_sync(0xFFFFFFFFu, cl, off);
    }
    int wid = tid >> 5, lid = tid & 31;
    if (lid == 0) { s_red[wid][0] = o; s_red[wid][1] = bb; s_red[wid][2] = cl; }
    __syncthreads();

    if (wid == 0) {
        double ro = (lid < 32) ? s_red[lid][0] : 0.0;
        double rb = (lid < 32) ? s_red[lid][1] : 0.0;
        double rc = (lid < 32) ? s_red[lid][2] : 0.0;
        #pragma unroll
        for (int off = 16; off > 0; off >>= 1) {
            ro += __shfl_down_sync(0xFFFFFFFFu, ro, off);
            rb += __shfl_down_sync(0xFFFFFFFFu, rb, off);
            rc += __shfl_down_sync(0xFFFFFFFFu, rc, off);
        }
        if (lid == 0) {
            float obj  = (float)(ro / (double)B);
            float bbox = (float)(rb / (double)B);
            float cls  = (float)(rc / (double)B);
            out[0] = 2.0f * obj + 5.0f * bbox + 2.0f * cls;
            out[1] = obj;
            out[2] = bbox;
            out[3] = cls;
        }
    }
}

extern "C" void kernel_launch(void* const* d_in, const int* in_sizes, int n_in,
                              void* d_out, int out_size)
{
    const float*     pred    = (const float*)d_in[0];
    const float*     tboxes  = (const float*)d_in[1];
    const long long* tlabels = (const long long*)d_in[2];
    const float*     anchors = (const float*)d_in[3];
    float*           out     = (float*)d_out;

    int B = in_sizes[0] / (AA * CH * HW);
    if (B > BB) B = BB;

    sgs_loss_per_batch<<<B, TPB>>>(pred, tboxes, tlabels, anchors);
    sgs_loss_reduce<<<1, 1024>>>(out, B);
}

// round 14
// speedup vs baseline: 1.7585x; 1.0887x over previous
#include <cuda_runtime.h>
#include <math.h>

// Problem constants (fixed by the reference)
#define BB    4096
#define AA    3
#define HH    13
#define WW    13
#define CC    5
#define NT    32
#define CH    (5 + CC)          // 10 channels per anchor
#define HW    (HH * WW)         // 169
#define NCELL (AA * HW)         // 507

#define TPB   256               // 8 warps per CTA, one batch per warp
#define WPB   8
#define NITW  16                // ceil(507/32) cells per lane

// Per-batch partial results, SoA for coalesced reduce.
__device__ float g_obj[BB];
__device__ float g_bbox[BB];
__device__ float g_cls[BB];

__device__ __forceinline__ float softplus_fast(float x) {
    // softplus(x) = max(x,0) + log(1+exp(-|x|)); fast-math (abs err < 1e-7)
    return fmaxf(x, 0.0f) + __logf(1.0f + __expf(-fabsf(x)));
}

__global__ void __launch_bounds__(TPB)
sgs_loss_per_batch(const float* __restrict__ pred,
                   const float* __restrict__ tboxes,
                   const long long* __restrict__ tlabels,
                   const float* __restrict__ anchors,
                   int B)
{
    // Per-warp private regions; 512-padded rows for alignment.
    __shared__ int   s_win[WPB][512];
    __shared__ int   s_win_cls[WPB][512];
    __shared__ float s_tbox[WPB][NT][4];
    __shared__ int   s_lab[WPB][NT];

    const int wid  = threadIdx.x >> 5;
    const int lane = threadIdx.x & 31;
    const int b    = blockIdx.x * WPB + wid;
    if (b >= B) return;                       // whole-warp uniform exit

    int*   win  = s_win[wid];
    int*   winc = s_win_cls[wid];
    const float* pb = pred + (size_t)b * (AA * CH * HW);

    // ---- init winner maps + prefetch obj logits (16 independent LDGs) ----
    float po[NITW];
    #pragma unroll
    for (int it = 0; it < NITW; it++) {
        int c = lane + it * 32;
        if (c < NCELL) { win[c] = -1; winc[c] = -1; }
        int a = c / HW, hw = c - a * HW;
        po[it] = (c < NCELL) ? pb[a * CH * HW + hw] : 0.0f;
    }
    __syncwarp();

    // ---- per-target processing (one target per lane; full warp active) ----
    {
        float4 box = ((const float4*)tboxes)[b * NT + lane];
        float cx = box.x, cy = box.y, w = box.z, h = box.w;
        bool valid = (cx > 0.0f) && (cx < 1.0f) && (cy > 0.0f) && (cy < 1.0f)
                  && (w > 0.0f) && (h > 0.0f);
        float ws = valid ? w : 1.0f;
        float hs = valid ? h : 1.0f;
        int gx = (int)(cx * (float)WW); gx = min(max(gx, 0), WW - 1);
        int gy = (int)(cy * (float)HH); gy = min(max(gy, 0), HH - 1);

        // argmax IoU over anchors (first occurrence on ties, matching jnp.argmax)
        int   besta = 0;
        float bestiou = -1.0f, baw = 1.0f, bah = 1.0f;
        #pragma unroll
        for (int a = 0; a < AA; a++) {
            float aw = anchors[a * 2 + 0];
            float ah = anchors[a * 2 + 1];
            float inter = fminf(ws, aw) * fminf(hs, ah);
            float iou = inter / (ws * hs + aw * ah - inter);
            if (iou > bestiou) { bestiou = iou; besta = a; baw = aw; bah = ah; }
        }

        s_tbox[wid][lane][0] = cx * (float)WW - (float)gx;
        s_tbox[wid][lane][1] = cy * (float)HH - (float)gy;
        s_tbox[wid][lane][2] = __logf(ws / baw + 1e-16f);   // feeds squared loss
        s_tbox[wid][lane][3] = __logf(hs / bah + 1e-16f);

        long long lb = tlabels[b * NT + lane];
        bool labok = (lb >= 0) && (lb < (long long)CC);
        long long lc = lb < 0 ? 0 : (lb > (long long)(CC - 1) ? (long long)(CC - 1) : lb);
        s_lab[wid][lane] = (int)lc;

        if (valid) {
            int cell = besta * HW + gy * WW + gx;
            atomicMax(&win[cell], lane);           // last-update-wins
            if (labok) atomicMax(&winc[cell], lane);
        }
    }
    __syncwarp();

    // ---- main loss over 507 cells (obj logits already in registers) ----
    float neg = 0.0f, pos = 0.0f, bsum = 0.0f, csum = 0.0f;
    int   cnt = 0;

    #pragma unroll
    for (int it = 0; it < NITW; it++) {
        int cidx = lane + it * 32;
        if (cidx >= NCELL) break;

        float sp = softplus_fast(po[it]);   // bce(x,0)=sp ; bce(x,1)=sp-x
        int wg = win[cidx];
        if (wg < 0) {
            neg += sp;
        } else {
            pos += sp - po[it];
            cnt++;
            int a  = cidx / HW;
            int hw = cidx - a * HW;
            const float* cp = pb + a * CH * HW + hw;
            #pragma unroll
            for (int j = 0; j < 4; j++) {
                float d = cp[(1 + j) * HW] - s_tbox[wid][wg][j];
                bsum += d * d;
            }
            int wc = winc[cidx];
            int lb = (wc >= 0) ? s_lab[wid][wc] : -1;
            #pragma unroll
            for (int c = 0; c < CC; c++) {
                float pc = cp[(5 + c) * HW];
                csum += softplus_fast(pc) - ((c == lb) ? pc : 0.0f);
            }
        }
    }

    // ---- warp reduction of {neg, pos, bsum, csum, cnt}; lane 0 writes ----
    float v[5] = {neg, pos, bsum, csum, (float)cnt};
    #pragma unroll
    for (int o = 16; o > 0; o >>= 1) {
        #pragma unroll
        for (int k = 0; k < 5; k++) v[k] += __shfl_down_sync(0xFFFFFFFFu, v[k], o);
    }

    if (lane == 0) {
        float npos = v[4];
        float pw = ((float)NCELL - npos) / (npos + 1e-16f);
        float obj_b  = (v[0] + pw * v[1]) / (float)NCELL;
        float bbox_b = (npos > 0.0f) ? v[2] / (4.0f * npos + 1e-30f) : 0.0f;
        float cls_b  = (npos > 0.0f) ? v[3] / ((float)CC * npos + 1e-30f) : 0.0f;
        g_obj[b]  = obj_b;
        g_bbox[b] = bbox_b;
        g_cls[b]  = cls_b;
    }
}

// 1024 threads: exactly one float4 per thread per array for B=4096.
__global__ void __launch_bounds__(1024)
sgs_loss_reduce(float* __restrict__ out, int B)
{
    __shared__ double s_red[32][3];
    const int tid = threadIdx.x;
    const int nvec = B >> 2;               // 1024 for B=4096

    double o = 0.0, bb = 0.0, cl = 0.0;
    for (int i = tid; i < nvec; i += 1024) {
        float4 vo = ((const float4*)g_obj)[i];
        float4 vb = ((const float4*)g_bbox)[i];
        float4 vc = ((const float4*)g_cls)[i];
        o  += (double)vo.x + (double)vo.y + (double)vo.z + (double)vo.w;
        bb += (double)vb.x + (double)vb.y + (double)vb.z + (double)vb.w;
        cl += (double)vc.x + (double)vc.y + (double)vc.z + (double)vc.w;
    }
    for (int i = (nvec << 2) + tid; i < B; i += 1024) {   // tail (empty for B=4096)
        o += (double)g_obj[i]; bb += (double)g_bbox[i]; cl += (double)g_cls[i];
    }

    #pragma unroll
    for (int off = 16; off > 0; off >>= 1) {
        o  += __shfl_down_sync(0xFFFFFFFFu, o,  off);
        bb += __shfl_down_sync(0xFFFFFFFFu, bb, off);
        cl += __shfl_down_sync(0xFFFFFFFFu, cl, off);
    }
    int wid = tid >> 5, lid = tid & 31;
    if (lid == 0) { s_red[wid][0] = o; s_red[wid][1] = bb; s_red[wid][2] = cl; }
    __syncthreads();

    if (wid == 0) {
        double ro = s_red[lid][0];
        double rb = s_red[lid][1];
        double rc = s_red[lid][2];
        #pragma unroll
        for (int off = 16; off > 0; off >>= 1) {
            ro += __shfl_down_sync(0xFFFFFFFFu, ro, off);
            rb += __shfl_down_sync(0xFFFFFFFFu, rb, off);
            rc += __shfl_down_sync(0xFFFFFFFFu, rc, off);
        }
        if (lid == 0) {
            float obj  = (float)(ro / (double)B);
            float bbox = (float)(rb / (double)B);
            float cls  = (float)(rc / (double)B);
            out[0] = 2.0f * obj + 5.0f * bbox + 2.0f * cls;
            out[1] = obj;
            out[2] = bbox;
            out[3] = cls;
        }
    }
}

extern "C" void kernel_launch(void* const* d_in, const int* in_sizes, int n_in,
                              void* d_out, int out_size)
{
    const float*     pred    = (const float*)d_in[0];
    const float*     tboxes  = (const float*)d_in[1];
    const long long* tlabels = (const long long*)d_in[2];
    const float*     anchors = (const float*)d_in[3];
    float*           out     = (float*)d_out;

    int B = in_sizes[0] / (AA * CH * HW);
    if (B > BB) B = BB;

    int nblk = (B + WPB - 1) / WPB;
    sgs_loss_per_batch<<<nblk, TPB>>>(pred, tboxes, tlabels, anchors, B);
    sgs_loss_reduce<<<1, 1024>>>(out, B);
}

// round 15
// speedup vs baseline: 1.7854x; 1.0153x over previous
#include <cuda_runtime.h>
#include <math.h>

// Problem constants (fixed by the reference)
#define BB    4096
#define AA    3
#define HH    13
#define WW    13
#define CC    5
#define NT    32
#define CH    (5 + CC)          // 10 channels per anchor
#define HW    (HH * WW)         // 169
#define NCELL (AA * HW)         // 507

#define TPB   256               // 8 warps per CTA, one batch per warp
#define WPB   8
#define NITW  16                // ceil(507/32) cells per lane

// Per-batch partial results, SoA for coalesced reduce.
__device__ float g_obj[BB];
__device__ float g_bbox[BB];
__device__ float g_cls[BB];

__device__ __forceinline__ float softplus_fast(float x) {
    // softplus(x) = max(x,0) + log(1+exp(-|x|)); fast-math (abs err < 1e-7)
    return fmaxf(x, 0.0f) + __logf(1.0f + __expf(-fabsf(x)));
}

__global__ void __launch_bounds__(TPB)
sgs_loss_per_batch(const float* __restrict__ pred,
                   const float* __restrict__ tboxes,
                   const long long* __restrict__ tlabels,
                   const float* __restrict__ anchors,
                   int B)
{
    // Per-warp private regions; 512-padded rows for alignment.
    __shared__ int   s_win[WPB][512];
    __shared__ int   s_win_cls[WPB][512];
    __shared__ float s_tbox[WPB][NT][4];
    __shared__ int   s_lab[WPB][NT];

    const int wid  = threadIdx.x >> 5;
    const int lane = threadIdx.x & 31;
    const int b    = blockIdx.x * WPB + wid;
    if (b >= B) return;                       // whole-warp uniform exit

    int*   win  = s_win[wid];
    int*   winc = s_win_cls[wid];
    const float* pb = pred + (size_t)b * (AA * CH * HW);

    // ---- init winner maps + prefetch obj logits (16 independent LDGs) ----
    float po[NITW];
    #pragma unroll
    for (int it = 0; it < NITW; it++) {
        int c = lane + it * 32;
        if (c < NCELL) { win[c] = -1; winc[c] = -1; }
        int a = c / HW, hw = c - a * HW;
        po[it] = (c < NCELL) ? pb[a * CH * HW + hw] : 0.0f;
    }
    __syncwarp();

    // ---- per-target processing (one target per lane; full warp active) ----
    {
        float4 box = ((const float4*)tboxes)[b * NT + lane];
        float cx = box.x, cy = box.y, w = box.z, h = box.w;
        bool valid = (cx > 0.0f) && (cx < 1.0f) && (cy > 0.0f) && (cy < 1.0f)
                  && (w > 0.0f) && (h > 0.0f);
        float ws = valid ? w : 1.0f;
        float hs = valid ? h : 1.0f;
        int gx = (int)(cx * (float)WW); gx = min(max(gx, 0), WW - 1);
        int gy = (int)(cy * (float)HH); gy = min(max(gy, 0), HH - 1);

        // argmax IoU over anchors (first occurrence on ties, matching jnp.argmax)
        int   besta = 0;
        float bestiou = -1.0f, baw = 1.0f, bah = 1.0f;
        #pragma unroll
        for (int a = 0; a < AA; a++) {
            float aw = anchors[a * 2 + 0];
            float ah = anchors[a * 2 + 1];
            float inter = fminf(ws, aw) * fminf(hs, ah);
            float iou = inter / (ws * hs + aw * ah - inter);
            if (iou > bestiou) { bestiou = iou; besta = a; baw = aw; bah = ah; }
        }

        s_tbox[wid][lane][0] = cx * (float)WW - (float)gx;
        s_tbox[wid][lane][1] = cy * (float)HH - (float)gy;
        s_tbox[wid][lane][2] = __logf(ws / baw + 1e-16f);   // feeds squared loss
        s_tbox[wid][lane][3] = __logf(hs / bah + 1e-16f);

        long long lb = tlabels[b * NT + lane];
        bool labok = (lb >= 0) && (lb < (long long)CC);
        long long lc = lb < 0 ? 0 : (lb > (long long)(CC - 1) ? (long long)(CC - 1) : lb);
        s_lab[wid][lane] = (int)lc;

        if (valid) {
            int cell = besta * HW + gy * WW + gx;
            atomicMax(&win[cell], lane);           // last-update-wins
            if (labok) atomicMax(&winc[cell], lane);
        }
    }
    __syncwarp();

    // ---- main loss over 507 cells (obj logits already in registers) ----
    float neg = 0.0f, pos = 0.0f, bsum = 0.0f, csum = 0.0f;
    int   cnt = 0;

    #pragma unroll
    for (int it = 0; it < NITW; it++) {
        int cidx = lane + it * 32;
        if (cidx >= NCELL) break;

        float sp = softplus_fast(po[it]);   // bce(x,0)=sp ; bce(x,1)=sp-x
        int wg = win[cidx];
        if (wg < 0) {
            neg += sp;
        } else {
            pos += sp - po[it];
            cnt++;
            int a  = cidx / HW;
            int hw = cidx - a * HW;
            const float* cp = pb + a * CH * HW + hw;
            #pragma unroll
            for (int j = 0; j < 4; j++) {
                float d = cp[(1 + j) * HW] - s_tbox[wid][wg][j];
                bsum += d * d;
            }
            int wc = winc[cidx];
            int lb = (wc >= 0) ? s_lab[wid][wc] : -1;
            #pragma unroll
            for (int c = 0; c < CC; c++) {
                float pc = cp[(5 + c) * HW];
                csum += softplus_fast(pc) - ((c == lb) ? pc : 0.0f);
            }
        }
    }

    // ---- warp reduction of {neg, pos, bsum, csum, cnt}; lane 0 writes ----
    float v[5] = {neg, pos, bsum, csum, (float)cnt};
    #pragma unroll
    for (int o = 16; o > 0; o >>= 1) {
        #pragma unroll
        for (int k = 0; k < 5; k++) v[k] += __shfl_down_sync(0xFFFFFFFFu, v[k], o);
    }

    if (lane == 0) {
        float npos = v[4];
        float pw = ((float)NCELL - npos) / (npos + 1e-16f);
        float obj_b  = (v[0] + pw * v[1]) / (float)NCELL;
        float bbox_b = (npos > 0.0f) ? v[2] / (4.0f * npos + 1e-30f) : 0.0f;
        float cls_b  = (npos > 0.0f) ? v[3] / ((float)CC * npos + 1e-30f) : 0.0f;
        g_obj[b]  = obj_b;
        g_bbox[b] = bbox_b;
        g_cls[b]  = cls_b;
    }
}

// 1024 threads: one float4 per thread per array for B=4096.
// Float accumulation (per-thread + warp tree); final 32-partial combine in double.
__global__ void __launch_bounds__(1024)
sgs_loss_reduce(float* __restrict__ out, int B)
{
    __shared__ float s_red[32][3];
    const int tid = threadIdx.x;
    const int nvec = B >> 2;               // 1024 for B=4096

    float o = 0.0f, bb = 0.0f, cl = 0.0f;
    for (int i = tid; i < nvec; i += 1024) {
        float4 vo = ((const float4*)g_obj)[i];
        float4 vb = ((const float4*)g_bbox)[i];
        float4 vc = ((const float4*)g_cls)[i];
        o  += (vo.x + vo.y) + (vo.z + vo.w);
        bb += (vb.x + vb.y) + (vb.z + vb.w);
        cl += (vc.x + vc.y) + (vc.z + vc.w);
    }
    for (int i = (nvec << 2) + tid; i < B; i += 1024) {   // tail (empty for B=4096)
        o += g_obj[i]; bb += g_bbox[i]; cl += g_cls[i];
    }

    #pragma unroll
    for (int off = 16; off > 0; off >>= 1) {
        o  += __shfl_down_sync(0xFFFFFFFFu, o,  off);
        bb += __shfl_down_sync(0xFFFFFFFFu, bb, off);
        cl += __shfl_down_sync(0xFFFFFFFFu, cl, off);
    }
    int wid = tid >> 5, lid = tid & 31;
    if (lid == 0) { s_red[wid][0] = o; s_red[wid][1] = bb; s_red[wid][2] = cl; }
    __syncthreads();

    if (tid == 0) {
        double ro = 0.0, rb = 0.0, rc = 0.0;
        #pragma unroll
        for (int w2 = 0; w2 < 32; w2++) {
            ro += (double)s_red[w2][0];
            rb += (double)s_red[w2][1];
            rc += (double)s_red[w2][2];
        }
        float obj  = (float)(ro / (double)B);
        float bbox = (float)(rb / (double)B);
        float cls  = (float)(rc / (double)B);
        out[0] = 2.0f * obj + 5.0f * bbox + 2.0f * cls;
        out[1] = obj;
        out[2] = bbox;
        out[3] = cls;
    }
}

extern "C" void kernel_launch(void* const* d_in, const int* in_sizes, int n_in,
                              void* d_out, int out_size)
{
    const float*     pred    = (const float*)d_in[0];
    const float*     tboxes  = (const float*)d_in[1];
    const long long* tlabels = (const long long*)d_in[2];
    const float*     anchors = (const float*)d_in[3];
    float*           out     = (float*)d_out;

    int B = in_sizes[0] / (AA * CH * HW);
    if (B > BB) B = BB;

    int nblk = (B + WPB - 1) / WPB;
    sgs_loss_per_batch<<<nblk, TPB>>>(pred, tboxes, tlabels, anchors, B);
    sgs_loss_reduce<<<1, 1024>>>(out, B);
}